// round 5
// baseline (speedup 1.0000x reference)
#include <cuda_runtime.h>
#include <cstdint>

#define F_DIM 16384
#define N_BINS 128
#define NT 256
#define N_ROWS 4096
#define N_OUT 64

// Prep outputs (allocation-free static scratch)
__device__ float g_wt[N_BINS * N_OUT];   // W[:, :128] transposed to [bin][out]
__device__ float g_s0[N_OUT];            // sum_j W[o][128+j]
__device__ float g_s1[N_OUT];            // sum_j (j/128) W[o][128+j]

__device__ __forceinline__ float f_inf() { return __int_as_float(0x7f800000); }

__device__ __forceinline__ uint32_t smem_u32(const void* p) {
    uint32_t a;
    asm("{ .reg .u64 t; cvta.to.shared.u64 t, %1; cvt.u32.u64 %0, t; }"
        : "=r"(a) : "l"(p));
    return a;
}
__device__ __forceinline__ uint32_t mapa_u32(uint32_t a, uint32_t rank) {
    uint32_t r;
    asm("mapa.shared::cluster.u32 %0, %1, %2;" : "=r"(r) : "r"(a), "r"(rank));
    return r;
}
__device__ __forceinline__ float ld_cluster_f32(uint32_t a) {
    float v;
    asm volatile("ld.shared::cluster.f32 %0, [%1];" : "=f"(v) : "r"(a));
    return v;
}
#define CLUSTER_SYNC()                                                   \
    do {                                                                 \
        asm volatile("barrier.cluster.arrive.aligned;" ::: "memory");    \
        asm volatile("barrier.cluster.wait.aligned;" ::: "memory");      \
    } while (0)

// ---------------------------------------------------------------------------
// Prep: one CTA per output o. Transpose counts-half of W to bin-major and
// reduce the 129 boundary weights to S0/S1.
// ---------------------------------------------------------------------------
__global__ __launch_bounds__(128) void prep_kernel(const float* __restrict__ W) {
    __shared__ float sp0[4], sp1[4];
    const int o = blockIdx.x;
    const int tid = threadIdx.x;

    g_wt[tid * N_OUT + o] = W[o * 257 + tid];

    float wv = W[o * 257 + 128 + tid];
    float s0 = wv;
    float s1 = (float)tid * 0.0078125f * wv;     // exact j/128
    if (tid == 0) {
        float w128 = W[o * 257 + 256];
        s0 += w128;
        s1 += w128;                               // t(128) = 1.0
    }
#pragma unroll
    for (int off = 16; off > 0; off >>= 1) {
        s0 += __shfl_xor_sync(0xFFFFFFFFu, s0, off);
        s1 += __shfl_xor_sync(0xFFFFFFFFu, s1, off);
    }
    if ((tid & 31) == 0) { sp0[tid >> 5] = s0; sp1[tid >> 5] = s1; }
    __syncthreads();
    if (tid == 0) {
        g_s0[o] = sp0[0] + sp0[1] + sp0[2] + sp0[3];
        g_s1[o] = sp1[0] + sp1[1] + sp1[2] + sp1[3];
    }
}

// ---------------------------------------------------------------------------
// Fused kernel: cluster of 2 CTAs per row; each CTA bins half the row
// (8 float4/thread, register-resident). Private u8 histograms per thread
// (conflict-free byte layout), RMW as 2 independent chains of 2 sequential
// updates (program order handles collisions). DSMEM exchanges the min/max
// partials and the per-half counts; rank 0 runs the fused matvec.
// ~50 regs -> 5 CTAs/SM (40 warps, occ ~62%), smem 34.9 KB static.
// ---------------------------------------------------------------------------
__global__ __launch_bounds__(NT, 5) __cluster_dims__(2, 1, 1)
void hist_kernel(const float* __restrict__ x,
                 const float* __restrict__ bias,
                 float* __restrict__ out) {
    __shared__ unsigned char s_hist[32768];
    __shared__ float s_red[32];     // 16 warp partials + CTA mn/mx at [16],[17]
    __shared__ float s_cnt[N_BINS];
    __shared__ float s_cnt2[N_BINS];
    __shared__ float s_part[NT];

    const int tid = threadIdx.x;
    const int row = blockIdx.x >> 1;
    uint32_t rank;
    asm("mov.u32 %0, %%cluster_ctarank;" : "=r"(rank));

    // ---- Issue loads for this CTA's half-row (8 float4 per thread) ----
    const float4* __restrict__ xr =
        (const float4*)(x + (size_t)row * F_DIM + rank * (F_DIM / 2));
    float4 rv[8];
#pragma unroll
    for (int i = 0; i < 8; i++) rv[i] = __ldcs(xr + tid + i * NT);

    // ---- Zero histogram while loads are in flight ----
    {
        uint4* hz = (uint4*)(s_hist + tid * 128);
        uint4 z = make_uint4(0u, 0u, 0u, 0u);
#pragma unroll
        for (int i = 0; i < 8; i++) hz[i] = z;
    }

    // ---- Intra-CTA min/max ----
    float mn = f_inf(), mx = -f_inf();
#pragma unroll
    for (int i = 0; i < 8; i++) {
        mn = fminf(mn, fminf(fminf(rv[i].x, rv[i].y), fminf(rv[i].z, rv[i].w)));
        mx = fmaxf(mx, fmaxf(fmaxf(rv[i].x, rv[i].y), fmaxf(rv[i].z, rv[i].w)));
    }
#pragma unroll
    for (int o = 16; o > 0; o >>= 1) {
        mn = fminf(mn, __shfl_xor_sync(0xFFFFFFFFu, mn, o));
        mx = fmaxf(mx, __shfl_xor_sync(0xFFFFFFFFu, mx, o));
    }
    if ((tid & 31) == 0) { s_red[tid >> 5] = mn; s_red[8 + (tid >> 5)] = mx; }
    __syncthreads();
    mn = s_red[0]; mx = s_red[8];
#pragma unroll
    for (int i = 1; i < 8; i++) { mn = fminf(mn, s_red[i]); mx = fmaxf(mx, s_red[8 + i]); }
    if (tid == 0) { s_red[16] = mn; s_red[17] = mx; }

    // ---- Cluster sync #1: partials visible; hist zeroed ----
    CLUSTER_SYNC();

    // Row-wide min/max: warp leaders read peer partials via DSMEM, broadcast
    {
        const uint32_t peer_red = mapa_u32(smem_u32(s_red), rank ^ 1u);
        float pmn = 0.0f, pmx = 0.0f;
        if ((tid & 31) == 0) {
            pmn = ld_cluster_f32(peer_red + 16 * 4);
            pmx = ld_cluster_f32(peer_red + 17 * 4);
        }
        pmn = __shfl_sync(0xFFFFFFFFu, pmn, 0);
        pmx = __shfl_sync(0xFFFFFFFFu, pmx, 0);
        mn = fminf(mn, pmn);
        mx = fmaxf(mx, pmx);
    }
    const float width = mx - mn;
    const float scale = 128.0f / (width == 0.0f ? 1.0f : width);  // matches jnp where()
    const float nb = -mn * scale;

    // ---- Bin: counter for (bin, t) at byte s_hist[bin*256 + 4*(t&63) + (t>>6)]
    // bank = t&31 for every lane -> conflict-free byte RMW, no atomics.
    unsigned char* hbase = s_hist + ((tid & 63) << 2) + (tid >> 6);
#pragma unroll
    for (int i = 0; i < 8; i++) {
        const float4 v = rv[i];
        const int b0 = (int)fminf(fmaf(v.x, scale, nb), 127.0f);
        const int b1 = (int)fminf(fmaf(v.y, scale, nb), 127.0f);
        const int b2 = (int)fminf(fmaf(v.z, scale, nb), 127.0f);
        const int b3 = (int)fminf(fmaf(v.w, scale, nb), 127.0f);
        // Two independent 2-deep chains; program order handles collisions.
        unsigned int c0 = hbase[b0 << 8];
        unsigned int c2 = hbase[b2 << 8];
        hbase[b0 << 8] = (unsigned char)(c0 + 1u);
        hbase[b2 << 8] = (unsigned char)(c2 + 1u);
        unsigned int c1 = hbase[b1 << 8];
        unsigned int c3 = hbase[b3 << 8];
        hbase[b1 << 8] = (unsigned char)(c1 + 1u);
        hbase[b3 << 8] = (unsigned char)(c3 + 1u);
    }
    __syncthreads();

    // ---- Reduce 64 words/bin: bin = tid>>1, each of a pair sums 32 words.
    // Packed u8 sums in u16 fields (max 32*32 < 65536), lane-rotated banks.
    {
        const unsigned int* h32 = (const unsigned int*)s_hist;
        const int bin = tid >> 1;
        const int base_w = (bin << 6) + ((tid & 1) << 5);
        const int r0 = tid & 31;
        unsigned int lo = 0, hi = 0;
#pragma unroll
        for (int j = 0; j < 32; j++) {
            unsigned int w = h32[base_w + ((r0 + j) & 31)];
            lo += w & 0x00FF00FFu;
            hi += (w >> 8) & 0x00FF00FFu;
        }
        unsigned int s = (lo & 0xFFFFu) + (lo >> 16) + (hi & 0xFFFFu) + (hi >> 16);
        s += __shfl_xor_sync(0xFFFFFFFFu, s, 1);
        if ((tid & 1) == 0) s_cnt[bin] = (float)s;
    }

    // ---- Cluster sync #2: both halves' counts ready ----
    CLUSTER_SYNC();

    // Combine own + peer counts
    {
        const uint32_t peer_cnt = mapa_u32(smem_u32(s_cnt), rank ^ 1u);
        if (tid < N_BINS)
            s_cnt2[tid] = s_cnt[tid] + ld_cluster_f32(peer_cnt + tid * 4);
    }

    // ---- Cluster sync #3: DSMEM reads complete -> peers free to exit ----
    CLUSTER_SYNC();

    if (rank != 0) return;

    // ---- Epilogue (rank 0): out[row][o] = cnt.Wt/F + mn*S0 + wd*S1 + b ----
    {
        const int o = tid & 63;
        const int q = tid >> 6;                   // 4 chunks of 32 bins
        const float* wt = g_wt + (q * 32) * N_OUT + o;
        float acc = 0.0f;
#pragma unroll
        for (int j = 0; j < 32; j++)
            acc = fmaf(s_cnt2[q * 32 + j], wt[j * N_OUT], acc);  // LDG L2-hot
        s_part[tid] = acc;
    }
    __syncthreads();
    if (tid < 64) {
        const float bo = bias[tid];
        float s = (s_part[tid] + s_part[tid + 64]) +
                  (s_part[tid + 128] + s_part[tid + 192]);
        float res = fmaf(s, 1.0f / 16384.0f,
                         fmaf(mn, g_s0[tid], fmaf(width, g_s1[tid], bo)));
        out[(size_t)row * N_OUT + tid] = res;
    }
}

// ---------------------------------------------------------------------------
extern "C" void kernel_launch(void* const* d_in, const int* in_sizes, int n_in,
                              void* d_out, int out_size) {
    const float* x = (const float*)d_in[0];
    const float* W = (const float*)d_in[1];
    const float* b = (const float*)d_in[2];
    float* out = (float*)d_out;

    prep_kernel<<<N_OUT, 128>>>(W);
    hist_kernel<<<N_ROWS * 2, NT>>>(x, b, out);
}

// round 7
// speedup vs baseline: 1.4899x; 1.4899x over previous
#include <cuda_runtime.h>
#include <cstdint>

#define F_DIM 16384
#define N_BINS 128
#define NT 256
#define N_ROWS 4096
#define N_OUT 64
#define N_STAGE 5            // float4 iterations staged in smem
#define N_REG 11             // float4 iterations kept in registers

// Prep outputs (allocation-free static scratch)
__device__ float g_wt[N_BINS * N_OUT];   // W[:, :128] transposed to [bin][out]
__device__ float g_s0[N_OUT];            // sum_j W[o][128+j]
__device__ float g_s1[N_OUT];            // sum_j (j/128) W[o][128+j]

__device__ __forceinline__ float f_inf() { return __int_as_float(0x7f800000); }

// ---------------------------------------------------------------------------
// Prep: one CTA per output o. Transpose counts-half of W to bin-major and
// reduce the 129 boundary weights to S0/S1.
// ---------------------------------------------------------------------------
__global__ __launch_bounds__(128) void prep_kernel(const float* __restrict__ W) {
    __shared__ float sp0[4], sp1[4];
    const int o = blockIdx.x;
    const int tid = threadIdx.x;

    g_wt[tid * N_OUT + o] = W[o * 257 + tid];

    float wv = W[o * 257 + 128 + tid];
    float s0 = wv;
    float s1 = (float)tid * 0.0078125f * wv;     // exact j/128
    if (tid == 0) {
        float w128 = W[o * 257 + 256];
        s0 += w128;
        s1 += w128;                               // t(128) = 1.0
    }
#pragma unroll
    for (int off = 16; off > 0; off >>= 1) {
        s0 += __shfl_xor_sync(0xFFFFFFFFu, s0, off);
        s1 += __shfl_xor_sync(0xFFFFFFFFu, s1, off);
    }
    if ((tid & 31) == 0) { sp0[tid >> 5] = s0; sp1[tid >> 5] = s1; }
    __syncthreads();
    if (tid == 0) {
        g_s0[o] = sp0[0] + sp0[1] + sp0[2] + sp0[3];
        g_s1[o] = sp1[0] + sp1[1] + sp1[2] + sp1[3];
    }
}

// ---------------------------------------------------------------------------
// Fused kernel: one CTA per row. 11 float4/thread in regs + 5 float4 staged
// in smem -> ~60 regs -> 4 CTAs/SM (32 warps). Private u8 histograms in a
// conflict-free byte layout. RMW: two 2-wave chains; only the concurrent
// pairs (b0,b2) and (b1,b3) need a merge compare — all other collisions are
// ordered by program-order char aliasing.
// SMEM (dynamic): [0,20K) staged data | [20K,52K) hist | red | cnt | part
// ---------------------------------------------------------------------------
__global__ __launch_bounds__(NT, 4) void hist_kernel(const float* __restrict__ x,
                                                     const float* __restrict__ bias,
                                                     float* __restrict__ out) {
    extern __shared__ unsigned char smem[];
    float4* sd4 = (float4*)smem;                              // 20480 B
    unsigned char* s_hist = smem + 20480;                     // 32768 B
    float* s_red = (float*)(smem + 20480 + 32768);            // 16 floats
    float* s_cnt = (float*)(smem + 20480 + 32768 + 64);       // 128 floats
    float* s_part = (float*)(smem + 20480 + 32768 + 64 + 512);// 256 floats

    const int tid = threadIdx.x;
    const int row = blockIdx.x;
    const float4* __restrict__ xr = (const float4*)(x + (size_t)row * F_DIM);

    // ---- Load row: first N_STAGE iterations to smem, rest to registers ----
    float mn = f_inf(), mx = -f_inf();
#pragma unroll
    for (int i = 0; i < N_STAGE; i++) {
        float4 v = __ldcs(xr + tid + i * NT);
        sd4[tid + i * NT] = v;
        mn = fminf(mn, fminf(fminf(v.x, v.y), fminf(v.z, v.w)));
        mx = fmaxf(mx, fmaxf(fmaxf(v.x, v.y), fmaxf(v.z, v.w)));
    }
    float4 rv[N_REG];
#pragma unroll
    for (int i = 0; i < N_REG; i++) {
        float4 v = __ldcs(xr + tid + (N_STAGE + i) * NT);
        rv[i] = v;
        mn = fminf(mn, fminf(fminf(v.x, v.y), fminf(v.z, v.w)));
        mx = fmaxf(mx, fmaxf(fmaxf(v.x, v.y), fmaxf(v.z, v.w)));
    }
#pragma unroll
    for (int o = 16; o > 0; o >>= 1) {
        mn = fminf(mn, __shfl_xor_sync(0xFFFFFFFFu, mn, o));
        mx = fmaxf(mx, __shfl_xor_sync(0xFFFFFFFFu, mx, o));
    }
    if ((tid & 31) == 0) { s_red[tid >> 5] = mn; s_red[8 + (tid >> 5)] = mx; }

    // ---- Zero histogram (each thread zeroes a contiguous 128 B chunk) ----
    {
        uint4* hz = (uint4*)(s_hist + tid * 128);
        uint4 z = make_uint4(0u, 0u, 0u, 0u);
#pragma unroll
        for (int i = 0; i < 8; i++) hz[i] = z;
    }
    __syncthreads();

    // Redundant final min/max reduce (no extra sync)
    mn = s_red[0]; mx = s_red[8];
#pragma unroll
    for (int i = 1; i < 8; i++) { mn = fminf(mn, s_red[i]); mx = fmaxf(mx, s_red[8 + i]); }
    const float width = mx - mn;
    const float scale = 128.0f / (width == 0.0f ? 1.0f : width);  // matches jnp where()
    const float nb = -mn * scale;

    // ---- Bin: counter for (bin, t) at byte s_hist[bin*256 + 4*(t&63) + (t>>6)]
    // bank = t&31 for every lane -> conflict-free byte RMW, no atomics.
    unsigned char* hbase = s_hist + ((tid & 63) << 2) + (tid >> 6);

#define BIN4(v)                                                                \
    {                                                                          \
        const int b0 = (int)fminf(fmaf((v).x, scale, nb), 127.0f);             \
        const int b1 = (int)fminf(fmaf((v).y, scale, nb), 127.0f);             \
        const int b2 = (int)fminf(fmaf((v).z, scale, nb), 127.0f);             \
        const int b3 = (int)fminf(fmaf((v).w, scale, nb), 127.0f);             \
        const unsigned int e02 = (b2 == b0) ? 1u : 0u;                         \
        const unsigned int e13 = (b3 == b1) ? 1u : 0u;                         \
        /* wave 1: loads of b0,b2 concurrent -> merged if equal */             \
        unsigned int c0 = hbase[b0 << 8];                                      \
        unsigned int c2 = hbase[b2 << 8];                                      \
        hbase[b0 << 8] = (unsigned char)(c0 + 1u + e02);                       \
        if (!e02) hbase[b2 << 8] = (unsigned char)(c2 + 1u);                   \
        /* wave 2: loads of b1,b3 after wave-1 stores (char aliasing) */       \
        unsigned int c1 = hbase[b1 << 8];                                      \
        unsigned int c3 = hbase[b3 << 8];                                      \
        hbase[b1 << 8] = (unsigned char)(c1 + 1u + e13);                       \
        if (!e13) hbase[b3 << 8] = (unsigned char)(c3 + 1u);                   \
    }

    // Register-resident values first
#pragma unroll
    for (int i = 0; i < N_REG; i++) BIN4(rv[i]);
    // Staged values
#pragma unroll
    for (int i = 0; i < N_STAGE; i++) {
        float4 v = sd4[tid + i * NT];
        BIN4(v);
    }
#undef BIN4
    __syncthreads();

    // ---- Reduce 64 words/bin: bin = tid>>1, each of a pair sums 32 words.
    // Packed u8 sums in u16 fields (max 64*32 < 65536), lane-rotated banks.
    {
        const unsigned int* h32 = (const unsigned int*)s_hist;
        const int bin = tid >> 1;
        const int base_w = (bin << 6) + ((tid & 1) << 5);
        const int r0 = tid & 31;
        unsigned int lo = 0, hi = 0;
#pragma unroll
        for (int j = 0; j < 32; j++) {
            unsigned int w = h32[base_w + ((r0 + j) & 31)];
            lo += w & 0x00FF00FFu;
            hi += (w >> 8) & 0x00FF00FFu;
        }
        unsigned int s = (lo & 0xFFFFu) + (lo >> 16) + (hi & 0xFFFFu) + (hi >> 16);
        s += __shfl_xor_sync(0xFFFFFFFFu, s, 1);
        if ((tid & 1) == 0) s_cnt[bin] = (float)s;
    }
    __syncthreads();

    // ---- Epilogue: out[row][o] = cnt.Wt/F + mn*S0 + wd*S1 + b ----
    {
        const int o = tid & 63;
        const int q = tid >> 6;                    // 4 chunks of 32 bins
        const float* wt = g_wt + (q * 32) * N_OUT + o;
        float acc = 0.0f;
#pragma unroll
        for (int j = 0; j < 32; j++)
            acc = fmaf(s_cnt[q * 32 + j], wt[j * N_OUT], acc);  // LDG L2-hot
        s_part[tid] = acc;
    }
    __syncthreads();
    if (tid < 64) {
        const float bo = bias[tid];
        float s = (s_part[tid] + s_part[tid + 64]) +
                  (s_part[tid + 128] + s_part[tid + 192]);
        float res = fmaf(s, 1.0f / 16384.0f,
                         fmaf(mn, g_s0[tid], fmaf(width, g_s1[tid], bo)));
        out[(size_t)row * N_OUT + tid] = res;
    }
}

// ---------------------------------------------------------------------------
extern "C" void kernel_launch(void* const* d_in, const int* in_sizes, int n_in,
                              void* d_out, int out_size) {
    const float* x = (const float*)d_in[0];
    const float* W = (const float*)d_in[1];
    const float* b = (const float*)d_in[2];
    float* out = (float*)d_out;

    const int smemA = 20480 + 32768 + 64 + 512 + 1024;   // 54848 B
    cudaFuncSetAttribute(hist_kernel, cudaFuncAttributeMaxDynamicSharedMemorySize, smemA);

    prep_kernel<<<N_OUT, 128>>>(W);
    hist_kernel<<<N_ROWS, NT, smemA>>>(x, b, out);
}

// round 8
// speedup vs baseline: 1.5533x; 1.0426x over previous
#include <cuda_runtime.h>
#include <cstdint>

#define F_DIM 16384
#define N_BINS 128
#define NT 256
#define N_ROWS 4096
#define N_OUT 64
#define GRID_P (152 * 3)     // persistent grid: 3 CTAs/SM on GB300 (152 SMs)

// Prep outputs (allocation-free static scratch)
__device__ float g_wt[N_BINS * N_OUT];   // W[:, :128] transposed to [bin][out]
__device__ float g_s0[N_OUT];            // sum_j W[o][128+j]
__device__ float g_s1[N_OUT];            // sum_j (j/128) W[o][128+j]

__device__ __forceinline__ float f_inf() { return __int_as_float(0x7f800000); }

// ---------------------------------------------------------------------------
// Prep: one CTA per output o. Transpose counts-half of W to bin-major and
// reduce the 129 boundary weights to S0/S1.
// ---------------------------------------------------------------------------
__global__ __launch_bounds__(128) void prep_kernel(const float* __restrict__ W) {
    __shared__ float sp0[4], sp1[4];
    const int o = blockIdx.x;
    const int tid = threadIdx.x;

    g_wt[tid * N_OUT + o] = W[o * 257 + tid];

    float wv = W[o * 257 + 128 + tid];
    float s0 = wv;
    float s1 = (float)tid * 0.0078125f * wv;     // exact j/128
    if (tid == 0) {
        float w128 = W[o * 257 + 256];
        s0 += w128;
        s1 += w128;                               // t(128) = 1.0
    }
#pragma unroll
    for (int off = 16; off > 0; off >>= 1) {
        s0 += __shfl_xor_sync(0xFFFFFFFFu, s0, off);
        s1 += __shfl_xor_sync(0xFFFFFFFFu, s1, off);
    }
    if ((tid & 31) == 0) { sp0[tid >> 5] = s0; sp1[tid >> 5] = s1; }
    __syncthreads();
    if (tid == 0) {
        g_s0[o] = sp0[0] + sp0[1] + sp0[2] + sp0[3];
        g_s1[o] = sp1[0] + sp1[1] + sp1[2] + sp1[3];
    }
}

// ---------------------------------------------------------------------------
// Persistent fused kernel: 456 CTAs, each ~9 rows. Row fully register-
// resident (16 float4/thread). While binning row r, the freed registers
// issue LDGs for row r+GRID_P -> DRAM overlaps the smem/ALU phases inside
// every warp. Private u8 histograms (conflict-free byte layout), safe
// pair-merged 2-wave RMW, dp4a hist reduce, fused matvec epilogue.
// SMEM static ~34.5 KB -> 3 CTAs/SM (reg-capped at 85 by launch_bounds).
// ---------------------------------------------------------------------------
__global__ __launch_bounds__(NT, 3) void hist_kernel(const float* __restrict__ x,
                                                     const float* __restrict__ bias,
                                                     float* __restrict__ out) {
    __shared__ unsigned char s_hist[32768];
    __shared__ float s_red[16];
    __shared__ float s_cnt[N_BINS];
    __shared__ float s_part[NT];

    const int tid = threadIdx.x;
    int row = blockIdx.x;

    // ---- Prologue: load row 0 of this CTA's sequence into registers ----
    float4 rv[16];
    {
        const float4* __restrict__ xr = (const float4*)(x + (size_t)row * F_DIM);
#pragma unroll
        for (int i = 0; i < 16; i++) rv[i] = __ldcs(xr + tid + i * NT);
    }

    float mn, width, scale, nb;
    // min/max of rv -> (mn, width, scale, nb). Involves 2 syncs.
    {
        float lmn = f_inf(), lmx = -f_inf();
#pragma unroll
        for (int i = 0; i < 16; i++) {
            lmn = fminf(lmn, fminf(fminf(rv[i].x, rv[i].y), fminf(rv[i].z, rv[i].w)));
            lmx = fmaxf(lmx, fmaxf(fmaxf(rv[i].x, rv[i].y), fmaxf(rv[i].z, rv[i].w)));
        }
#pragma unroll
        for (int o = 16; o > 0; o >>= 1) {
            lmn = fminf(lmn, __shfl_xor_sync(0xFFFFFFFFu, lmn, o));
            lmx = fmaxf(lmx, __shfl_xor_sync(0xFFFFFFFFu, lmx, o));
        }
        if ((tid & 31) == 0) { s_red[tid >> 5] = lmn; s_red[8 + (tid >> 5)] = lmx; }
        __syncthreads();
        lmn = s_red[0]; lmx = s_red[8];
#pragma unroll
        for (int i = 1; i < 8; i++) {
            lmn = fminf(lmn, s_red[i]);
            lmx = fmaxf(lmx, s_red[8 + i]);
        }
        mn = lmn;
        width = lmx - lmn;
        scale = 128.0f / (width == 0.0f ? 1.0f : width);   // matches jnp where()
        nb = -mn * scale;
        __syncthreads();   // s_red free for reuse
    }

    for (;;) {
        const int next = row + GRID_P;
        const bool has_next = (next < N_ROWS);
        const float4* __restrict__ nxt =
            (const float4*)(x + (size_t)(has_next ? next : row) * F_DIM);

        // ---- Zero histogram (each thread a contiguous 128 B chunk) ----
        {
            uint4* hz = (uint4*)(s_hist + tid * 128);
            uint4 z = make_uint4(0u, 0u, 0u, 0u);
#pragma unroll
            for (int i = 0; i < 8; i++) hz[i] = z;
        }
        __syncthreads();

        // ---- Bin current row; per group, refill rv[i] with next row's LDG.
        // Counter for (bin, t) at byte s_hist[bin*256 + 4*(t&63) + (t>>6)]
        // -> bank = t&31 for every lane: conflict-free byte RMW, no atomics.
        unsigned char* hbase = s_hist + ((tid & 63) << 2) + (tid >> 6);
#pragma unroll
        for (int i = 0; i < 16; i++) {
            const float4 v = rv[i];
            if (has_next) rv[i] = __ldcs(nxt + tid + i * NT);   // prefetch
            const int b0 = (int)fminf(fmaf(v.x, scale, nb), 127.0f);
            const int b1 = (int)fminf(fmaf(v.y, scale, nb), 127.0f);
            const int b2 = (int)fminf(fmaf(v.z, scale, nb), 127.0f);
            const int b3 = (int)fminf(fmaf(v.w, scale, nb), 127.0f);
            const unsigned int e02 = (b2 == b0) ? 1u : 0u;
            const unsigned int e13 = (b3 == b1) ? 1u : 0u;
            // wave 1: loads of b0,b2 concurrent -> merged if equal
            unsigned int c0 = hbase[b0 << 8];
            unsigned int c2 = hbase[b2 << 8];
            hbase[b0 << 8] = (unsigned char)(c0 + 1u + e02);
            if (!e02) hbase[b2 << 8] = (unsigned char)(c2 + 1u);
            // wave 2: loads of b1,b3 after wave-1 stores (char aliasing)
            unsigned int c1 = hbase[b1 << 8];
            unsigned int c3 = hbase[b3 << 8];
            hbase[b1 << 8] = (unsigned char)(c1 + 1u + e13);
            if (!e13) hbase[b3 << 8] = (unsigned char)(c3 + 1u);
        }
        __syncthreads();

        // ---- Reduce 64 words/bin: bin = tid>>1, each of a pair sums 32
        // words via dp4a (bytes <= 64, no overflow), lane-rotated banks.
        {
            const unsigned int* h32 = (const unsigned int*)s_hist;
            const int bin = tid >> 1;
            const int base_w = (bin << 6) + ((tid & 1) << 5);
            const int r0 = tid & 31;
            unsigned int s = 0;
#pragma unroll
            for (int j = 0; j < 32; j++)
                s = __dp4a(h32[base_w + ((r0 + j) & 31)], 0x01010101u, s);
            s += __shfl_xor_sync(0xFFFFFFFFu, s, 1);
            if ((tid & 1) == 0) s_cnt[bin] = (float)s;
        }
        __syncthreads();

        // ---- Epilogue: out[row][o] = cnt.Wt/F + mn*S0 + wd*S1 + b ----
        {
            const int o = tid & 63;
            const int q = tid >> 6;                    // 4 chunks of 32 bins
            const float* wt = g_wt + (q * 32) * N_OUT + o;
            float acc = 0.0f;
#pragma unroll
            for (int j = 0; j < 32; j++)
                acc = fmaf(s_cnt[q * 32 + j], __ldg(wt + j * N_OUT), acc);
            s_part[tid] = acc;
        }
        __syncthreads();
        if (tid < 64) {
            const float bo = bias[tid];
            float s = (s_part[tid] + s_part[tid + 64]) +
                      (s_part[tid + 128] + s_part[tid + 192]);
            float res = fmaf(s, 1.0f / 16384.0f,
                             fmaf(mn, g_s0[tid], fmaf(width, g_s1[tid], bo)));
            out[(size_t)row * N_OUT + tid] = res;
        }

        if (!has_next) break;
        row = next;

        // ---- min/max of the freshly prefetched row (scoreboard waits) ----
        {
            float lmn = f_inf(), lmx = -f_inf();
#pragma unroll
            for (int i = 0; i < 16; i++) {
                lmn = fminf(lmn, fminf(fminf(rv[i].x, rv[i].y), fminf(rv[i].z, rv[i].w)));
                lmx = fmaxf(lmx, fmaxf(fmaxf(rv[i].x, rv[i].y), fmaxf(rv[i].z, rv[i].w)));
            }
#pragma unroll
            for (int o = 16; o > 0; o >>= 1) {
                lmn = fminf(lmn, __shfl_xor_sync(0xFFFFFFFFu, lmn, o));
                lmx = fmaxf(lmx, __shfl_xor_sync(0xFFFFFFFFu, lmx, o));
            }
            __syncthreads();   // s_part reads done -> s_red safe to overwrite
            if ((tid & 31) == 0) { s_red[tid >> 5] = lmn; s_red[8 + (tid >> 5)] = lmx; }
            __syncthreads();
            lmn = s_red[0]; lmx = s_red[8];
#pragma unroll
            for (int i = 1; i < 8; i++) {
                lmn = fminf(lmn, s_red[i]);
                lmx = fmaxf(lmx, s_red[8 + i]);
            }
            mn = lmn;
            width = lmx - lmn;
            scale = 128.0f / (width == 0.0f ? 1.0f : width);
            nb = -mn * scale;
        }
        __syncthreads();   // s_red consumed by all before next overwrite
    }
}

// ---------------------------------------------------------------------------
extern "C" void kernel_launch(void* const* d_in, const int* in_sizes, int n_in,
                              void* d_out, int out_size) {
    const float* x = (const float*)d_in[0];
    const float* W = (const float*)d_in[1];
    const float* b = (const float*)d_in[2];
    float* out = (float*)d_out;

    prep_kernel<<<N_OUT, 128>>>(W);
    hist_kernel<<<GRID_P, NT>>>(x, b, out);
}

// round 10
// speedup vs baseline: 1.5913x; 1.0245x over previous
#include <cuda_runtime.h>
#include <cstdint>

#define F_DIM 16384
#define N_BINS 128
#define NT 256
#define N_ROWS 4096
#define N_OUT 64
#define GRID_P (152 * 3)      // persistent grid: 3 CTAs/SM on GB300 (152 SMs)
#define HIST_WB 4608          // per-warp hist bytes: 128 bins * 36 B (9-word pad)

// Prep outputs (allocation-free static scratch)
__device__ float g_wt[N_BINS * N_OUT];   // W[:, :128] transposed to [bin][out]
__device__ float g_s0[N_OUT];            // sum_j W[o][128+j]
__device__ float g_s1[N_OUT];            // sum_j (j/128) W[o][128+j]

__device__ __forceinline__ float f_inf() { return __int_as_float(0x7f800000); }

// ---------------------------------------------------------------------------
// Prep: one CTA per output o. Transpose counts-half of W to bin-major and
// reduce the 129 boundary weights to S0/S1.
// ---------------------------------------------------------------------------
__global__ __launch_bounds__(128) void prep_kernel(const float* __restrict__ W) {
    __shared__ float sp0[4], sp1[4];
    const int o = blockIdx.x;
    const int tid = threadIdx.x;

    g_wt[tid * N_OUT + o] = W[o * 257 + tid];

    float wv = W[o * 257 + 128 + tid];
    float s0 = wv;
    float s1 = (float)tid * 0.0078125f * wv;     // exact j/128
    if (tid == 0) {
        float w128 = W[o * 257 + 256];
        s0 += w128;
        s1 += w128;                               // t(128) = 1.0
    }
#pragma unroll
    for (int off = 16; off > 0; off >>= 1) {
        s0 += __shfl_xor_sync(0xFFFFFFFFu, s0, off);
        s1 += __shfl_xor_sync(0xFFFFFFFFu, s1, off);
    }
    if ((tid & 31) == 0) { sp0[tid >> 5] = s0; sp1[tid >> 5] = s1; }
    __syncthreads();
    if (tid == 0) {
        g_s0[o] = sp0[0] + sp0[1] + sp0[2] + sp0[3];
        g_s1[o] = sp1[0] + sp1[1] + sp1[2] + sp1[3];
    }
}

// ---------------------------------------------------------------------------
// Persistent fused kernel, warp-private histograms. Per row:
//   JOIN A (minmax) -> [warp-local: zero 4.6KB, bin 64 vals, reduce+pcnt]
//   -> JOIN B -> combine 8 warps -> JOIN B2 -> epilogue -> JOIN C.
// zero/bin/reduce are barrier-free across warps -> warps drift, phases of
// different warps overlap, DRAM/L1/ALU demand mixes continuously.
// Layouts (all bank-analyzed):
//   hist byte (w,b,l): w*4608 + b*36 + l   RMW bank (9b + l/4)&31
//   reduce: lane l sums bins l+32k, words 9b..9b+7 -> bank (9l+j)&31  CF
//   pcnt[b*9 + w] -> bank (9l + w)&31 over lane bins                  CF
// ---------------------------------------------------------------------------
__global__ __launch_bounds__(NT, 3) void hist_kernel(const float* __restrict__ x,
                                                     const float* __restrict__ bias,
                                                     float* __restrict__ out) {
    __shared__ unsigned char s_hist[8 * HIST_WB];   // 36864 B
    __shared__ float s_red[16];
    __shared__ int   s_pcnt[N_BINS * 9];            // 4608 B
    __shared__ float s_cnt[N_BINS];
    __shared__ float s_part[NT];

    const int tid = threadIdx.x;
    const int w = tid >> 5;
    const int l = tid & 31;
    int row = blockIdx.x;

    // ---- Prologue: load first row into registers ----
    float4 rv[16];
    {
        const float4* __restrict__ xr = (const float4*)(x + (size_t)row * F_DIM);
#pragma unroll
        for (int i = 0; i < 16; i++) rv[i] = __ldcs(xr + tid + i * NT);
    }

    for (;;) {
        const int next = row + GRID_P;
        const bool has_next = (next < N_ROWS);
        const float4* __restrict__ nxt =
            (const float4*)(x + (size_t)(has_next ? next : row) * F_DIM);

        // ---- Warp min/max partial ----
        float mn = f_inf(), mx = -f_inf();
#pragma unroll
        for (int i = 0; i < 16; i++) {
            mn = fminf(mn, fminf(fminf(rv[i].x, rv[i].y), fminf(rv[i].z, rv[i].w)));
            mx = fmaxf(mx, fmaxf(fmaxf(rv[i].x, rv[i].y), fmaxf(rv[i].z, rv[i].w)));
        }
#pragma unroll
        for (int o = 16; o > 0; o >>= 1) {
            mn = fminf(mn, __shfl_xor_sync(0xFFFFFFFFu, mn, o));
            mx = fmaxf(mx, __shfl_xor_sync(0xFFFFFFFFu, mx, o));
        }
        if (l == 0) { s_red[w] = mn; s_red[8 + w] = mx; }
        __syncthreads();                               // JOIN A
        mn = s_red[0]; mx = s_red[8];
#pragma unroll
        for (int i = 1; i < 8; i++) { mn = fminf(mn, s_red[i]); mx = fmaxf(mx, s_red[8 + i]); }
        const float width = mx - mn;
        const float scale = 128.0f / (width == 0.0f ? 1.0f : width);  // matches jnp where()
        const float nb = -mn * scale;

        // ---- Zero own warp hist (warp-local, conflict-free) ----
        {
            uint4* hz = (uint4*)(s_hist + w * HIST_WB);
            uint4 z = make_uint4(0u, 0u, 0u, 0u);
#pragma unroll
            for (int k = 0; k < 9; k++) hz[l * 9 + k] = z;
        }
        __syncwarp();

        // ---- Bin 64 values (warp-local); interleave next-row prefetch ----
        unsigned char* hb = s_hist + w * HIST_WB + l;
#pragma unroll
        for (int i = 0; i < 16; i++) {
            const float4 v = rv[i];
            if (has_next) rv[i] = __ldcs(nxt + tid + i * NT);   // prefetch
            const int b0 = (int)fminf(fmaf(v.x, scale, nb), 127.0f);
            const int b1 = (int)fminf(fmaf(v.y, scale, nb), 127.0f);
            const int b2 = (int)fminf(fmaf(v.z, scale, nb), 127.0f);
            const int b3 = (int)fminf(fmaf(v.w, scale, nb), 127.0f);
            const int o0 = b0 * 36, o1 = b1 * 36, o2 = b2 * 36, o3 = b3 * 36;
            const unsigned int e02 = (b2 == b0) ? 1u : 0u;
            const unsigned int e13 = (b3 == b1) ? 1u : 0u;
            // wave 1: loads of b0,b2 concurrent -> merged if equal
            unsigned int c0 = hb[o0];
            unsigned int c2 = hb[o2];
            hb[o0] = (unsigned char)(c0 + 1u + e02);
            if (!e02) hb[o2] = (unsigned char)(c2 + 1u);
            // wave 2: loads of b1,b3 after wave-1 stores (char aliasing)
            unsigned int c1 = hb[o1];
            unsigned int c3 = hb[o3];
            hb[o1] = (unsigned char)(c1 + 1u + e13);
            if (!e13) hb[o3] = (unsigned char)(c3 + 1u);
        }
        __syncwarp();

        // ---- Warp-local reduce: lane l sums bins l, l+32, l+64, l+96 ----
        {
            const unsigned int* h32 = (const unsigned int*)(s_hist + w * HIST_WB);
#pragma unroll
            for (int k = 0; k < 4; k++) {
                const int b = l + 32 * k;
                const int base = b * 9;
                unsigned int s = 0u;
#pragma unroll
                for (int j = 0; j < 8; j++)
                    s = __dp4a(h32[base + j], 0x01010101u, s);   // uint overload
                s_pcnt[base + w] = (int)s;         // bank (9l + w)&31: CF
            }
        }
        __syncthreads();                               // JOIN B

        // ---- Combine the 8 warps' partial counts ----
        if (tid < N_BINS) {
            const int base = tid * 9;
            int s = 0;
#pragma unroll
            for (int w2 = 0; w2 < 8; w2++) s += s_pcnt[base + w2];
            s_cnt[tid] = (float)s;
        }
        __syncthreads();                               // JOIN B2

        // ---- Epilogue: out[row][o] = cnt.Wt/F + mn*S0 + wd*S1 + b ----
        {
            const int o = tid & 63;
            const int q = tid >> 6;                    // 4 chunks of 32 bins
            const float* wt = g_wt + (q * 32) * N_OUT + o;
            float acc = 0.0f;
#pragma unroll
            for (int j = 0; j < 32; j++)
                acc = fmaf(s_cnt[q * 32 + j], __ldg(wt + j * N_OUT), acc);
            s_part[tid] = acc;
        }
        __syncthreads();                               // JOIN C
        if (tid < 64) {
            const float bo = bias[tid];
            float s = (s_part[tid] + s_part[tid + 64]) +
                      (s_part[tid + 128] + s_part[tid + 192]);
            float res = fmaf(s, 1.0f / 16384.0f,
                             fmaf(mn, g_s0[tid], fmaf(width, g_s1[tid], bo)));
            out[(size_t)row * N_OUT + tid] = res;
        }

        if (!has_next) break;
        row = next;
    }
}

// ---------------------------------------------------------------------------
extern "C" void kernel_launch(void* const* d_in, const int* in_sizes, int n_in,
                              void* d_out, int out_size) {
    const float* x = (const float*)d_in[0];
    const float* W = (const float*)d_in[1];
    const float* b = (const float*)d_in[2];
    float* out = (float*)d_out;

    prep_kernel<<<N_OUT, 128>>>(W);
    hist_kernel<<<GRID_P, NT>>>(x, b, out);
}

// round 12
// speedup vs baseline: 2.0475x; 1.2866x over previous
#include <cuda_runtime.h>
#include <cstdint>

#define F_DIM 16384
#define N_BINS 128
#define NT 256
#define N_ROWS 4096
#define N_OUT 64
#define GRID_P (152 * 3)      // persistent grid: 3 CTAs/SM on GB300 (152 SMs)

// Prep outputs (allocation-free static scratch)
__device__ float g_wt[N_BINS * N_OUT];   // W[:, :128] transposed to [bin][out]
__device__ float g_s0[N_OUT];            // sum_j W[o][128+j]
__device__ float g_s1[N_OUT];            // sum_j (j/128) W[o][128+j]

__device__ __forceinline__ float f_inf() { return __int_as_float(0x7f800000); }

// ---------------------------------------------------------------------------
// Prep: one CTA per output o. Transpose counts-half of W to bin-major and
// reduce the 129 boundary weights to S0/S1.
// ---------------------------------------------------------------------------
__global__ __launch_bounds__(128) void prep_kernel(const float* __restrict__ W) {
    __shared__ float sp0[4], sp1[4];
    const int o = blockIdx.x;
    const int tid = threadIdx.x;

    g_wt[tid * N_OUT + o] = W[o * 257 + tid];

    float wv = W[o * 257 + 128 + tid];
    float s0 = wv;
    float s1 = (float)tid * 0.0078125f * wv;     // exact j/128
    if (tid == 0) {
        float w128 = W[o * 257 + 256];
        s0 += w128;
        s1 += w128;                               // t(128) = 1.0
    }
#pragma unroll
    for (int off = 16; off > 0; off >>= 1) {
        s0 += __shfl_xor_sync(0xFFFFFFFFu, s0, off);
        s1 += __shfl_xor_sync(0xFFFFFFFFu, s1, off);
    }
    if ((tid & 31) == 0) { sp0[tid >> 5] = s0; sp1[tid >> 5] = s1; }
    __syncthreads();
    if (tid == 0) {
        g_s0[o] = sp0[0] + sp0[1] + sp0[2] + sp0[3];
        g_s1[o] = sp1[0] + sp1[1] + sp1[2] + sp1[3];
    }
}

// ---------------------------------------------------------------------------
// Persistent fused kernel, warp-private histograms with a bank-invariant
// layout: counter (w, b, l) at byte  w*4096 + (b>>2)*128 + l*4 + (b&3).
//   word = w*1024 + (b>>2)*32 + l  ->  bank = l  for ANY bin value.
// => the byte RMW is conflict-free by construction (1 wavefront/instr),
// unlike R10's b*36+l layout whose bank depended on the data. 4 KB/warp.
// Per row: JOIN A (minmax) -> warp-local zero/bin/reduce -> JOIN B ->
// combine -> JOIN B2 -> epilogue -> JOIN C.
// ---------------------------------------------------------------------------
__global__ __launch_bounds__(NT, 3) void hist_kernel(const float* __restrict__ x,
                                                     const float* __restrict__ bias,
                                                     float* __restrict__ out) {
    __shared__ unsigned char s_hist[8 * 4096];      // 32768 B
    __shared__ float s_red[16];
    __shared__ int   s_pcnt[N_BINS * 9];            // stride 9: CF combine
    __shared__ float s_cnt[N_BINS];
    __shared__ float s_part[NT];

    const int tid = threadIdx.x;
    const int w = tid >> 5;
    const int l = tid & 31;
    int row = blockIdx.x;

    // ---- Prologue: load first row into registers ----
    float4 rv[16];
    {
        const float4* __restrict__ xr = (const float4*)(x + (size_t)row * F_DIM);
#pragma unroll
        for (int i = 0; i < 16; i++) rv[i] = __ldcs(xr + tid + i * NT);
    }

    for (;;) {
        const int next = row + GRID_P;
        const bool has_next = (next < N_ROWS);
        const float4* __restrict__ nxt =
            (const float4*)(x + (size_t)(has_next ? next : row) * F_DIM);

        // ---- Warp min/max partial ----
        float mn = f_inf(), mx = -f_inf();
#pragma unroll
        for (int i = 0; i < 16; i++) {
            mn = fminf(mn, fminf(fminf(rv[i].x, rv[i].y), fminf(rv[i].z, rv[i].w)));
            mx = fmaxf(mx, fmaxf(fmaxf(rv[i].x, rv[i].y), fmaxf(rv[i].z, rv[i].w)));
        }
#pragma unroll
        for (int o = 16; o > 0; o >>= 1) {
            mn = fminf(mn, __shfl_xor_sync(0xFFFFFFFFu, mn, o));
            mx = fmaxf(mx, __shfl_xor_sync(0xFFFFFFFFu, mx, o));
        }
        if (l == 0) { s_red[w] = mn; s_red[8 + w] = mx; }
        __syncthreads();                               // JOIN A
        mn = s_red[0]; mx = s_red[8];
#pragma unroll
        for (int i = 1; i < 8; i++) { mn = fminf(mn, s_red[i]); mx = fmaxf(mx, s_red[8 + i]); }
        const float width = mx - mn;
        const float scale = 128.0f / (width == 0.0f ? 1.0f : width);  // matches jnp where()
        const float nb = -mn * scale;

        // ---- Zero own warp hist: 8 STS.128, lanes spread across banks ----
        {
            uint4* hz = (uint4*)(s_hist + (w << 12));
            uint4 z = make_uint4(0u, 0u, 0u, 0u);
#pragma unroll
            for (int k = 0; k < 8; k++) hz[k * 32 + l] = z;
        }
        __syncwarp();

        // ---- Bin 64 values (warp-local, bank-CF); interleave prefetch ----
        unsigned char* hb = s_hist + (w << 12) + (l << 2);
#pragma unroll
        for (int i = 0; i < 16; i++) {
            const float4 v = rv[i];
            if (has_next) rv[i] = __ldcs(nxt + tid + i * NT);   // prefetch
            const int b0 = (int)fminf(fmaf(v.x, scale, nb), 127.0f);
            const int b1 = (int)fminf(fmaf(v.y, scale, nb), 127.0f);
            const int b2 = (int)fminf(fmaf(v.z, scale, nb), 127.0f);
            const int b3 = (int)fminf(fmaf(v.w, scale, nb), 127.0f);
            // byte offset: (b>>2)*128 + (b&3) = ((b & 124) << 5) + (b & 3)
            const int o0 = ((b0 & 124) << 5) + (b0 & 3);
            const int o1 = ((b1 & 124) << 5) + (b1 & 3);
            const int o2 = ((b2 & 124) << 5) + (b2 & 3);
            const int o3 = ((b3 & 124) << 5) + (b3 & 3);
            const unsigned int e02 = (b2 == b0) ? 1u : 0u;
            const unsigned int e13 = (b3 == b1) ? 1u : 0u;
            // wave 1: loads of b0,b2 concurrent -> merged if equal
            unsigned int c0 = hb[o0];
            unsigned int c2 = hb[o2];
            hb[o0] = (unsigned char)(c0 + 1u + e02);
            if (!e02) hb[o2] = (unsigned char)(c2 + 1u);
            // wave 2: loads of b1,b3 after wave-1 stores (char aliasing)
            unsigned int c1 = hb[o1];
            unsigned int c3 = hb[o3];
            hb[o1] = (unsigned char)(c1 + 1u + e13);
            if (!e13) hb[o3] = (unsigned char)(c3 + 1u);
        }
        __syncwarp();

        // ---- Warp-local reduce: lane l owns bins 4l..4l+3 (word row l).
        // Rotated reads: word l*32 + (j+l)&31 -> bank (j+l)&31, CF.
        // Packed u16 fields: lo = bins (4l, 4l+2), hi = bins (4l+1, 4l+3);
        // max 32 words * 64 = 2048 < 65536.
        {
            const unsigned int* h32 = (const unsigned int*)(s_hist + (w << 12));
            unsigned int lo = 0u, hi = 0u;
#pragma unroll
            for (int j = 0; j < 32; j++) {
                unsigned int v32 = h32[(l << 5) + ((j + l) & 31)];
                lo += v32 & 0x00FF00FFu;
                hi += (v32 >> 8) & 0x00FF00FFu;
            }
            const int b4 = l << 2;
            s_pcnt[(b4 + 0) * 9 + w] = (int)(lo & 0xFFFFu);
            s_pcnt[(b4 + 1) * 9 + w] = (int)(hi & 0xFFFFu);
            s_pcnt[(b4 + 2) * 9 + w] = (int)(lo >> 16);
            s_pcnt[(b4 + 3) * 9 + w] = (int)(hi >> 16);
        }
        __syncthreads();                               // JOIN B

        // ---- Combine the 8 warps' partials (stride 9 -> CF banks) ----
        if (tid < N_BINS) {
            const int base = tid * 9;
            int s = 0;
#pragma unroll
            for (int w2 = 0; w2 < 8; w2++) s += s_pcnt[base + w2];
            s_cnt[tid] = (float)s;
        }
        __syncthreads();                               // JOIN B2

        // ---- Epilogue: out[row][o] = cnt.Wt/F + mn*S0 + wd*S1 + b ----
        {
            const int o = tid & 63;
            const int q = tid >> 6;                    // 4 chunks of 32 bins
            const float* wt = g_wt + (q * 32) * N_OUT + o;
            float acc = 0.0f;
#pragma unroll
            for (int j = 0; j < 32; j++)
                acc = fmaf(s_cnt[q * 32 + j], __ldg(wt + j * N_OUT), acc);
            s_part[tid] = acc;
        }
        __syncthreads();                               // JOIN C
        if (tid < 64) {
            const float bo = bias[tid];
            float s = (s_part[tid] + s_part[tid + 64]) +
                      (s_part[tid + 128] + s_part[tid + 192]);
            float res = fmaf(s, 1.0f / 16384.0f,
                             fmaf(mn, g_s0[tid], fmaf(width, g_s1[tid], bo)));
            out[(size_t)row * N_OUT + tid] = res;
        }

        if (!has_next) break;
        row = next;
    }
}

// ---------------------------------------------------------------------------
extern "C" void kernel_launch(void* const* d_in, const int* in_sizes, int n_in,
                              void* d_out, int out_size) {
    const float* x = (const float*)d_in[0];
    const float* W = (const float*)d_in[1];
    const float* b = (const float*)d_in[2];
    float* out = (float*)d_out;

    prep_kernel<<<N_OUT, 128>>>(W);
    hist_kernel<<<GRID_P, NT>>>(x, b, out);
}